// round 13
// baseline (speedup 1.0000x reference)
#include <cuda_runtime.h>
#include <cuda_fp16.h>
#include <cstdint>
#include <math.h>

#define T_STEPS 256
#define BB      256
#define HH      512
#define H4      2048
#define NBLK    4

// ---------------- static device scratch ----------------
__device__ float  d_X [T_STEPS*BB*HH];
__device__ __half d_XN[T_STEPS*BB*HH];
__device__ float  d_Y [T_STEPS*BB*HH];
__device__ __half d_YN[T_STEPS*BB*HH];
__device__ __half d_G [(size_t)T_STEPS*BB*H4];
__device__ __half d_FC[(size_t)T_STEPS*BB*H4];
__device__ __half d_h0[BB*HH];                   // chunked+swizzled (see lstm kernel)
__device__ __half d_h1[BB*HH];
__device__ __half d_Wih [NBLK*H4*HH];
__device__ __half d_Wfc [NBLK*H4*HH];
__device__ __half d_Wpr [NBLK*HH*H4];
__device__ __half d_Whh [NBLK*H4*HH];
__device__ unsigned d_bar[4];
__device__ int g_idx_stride;

// ---------------- ptx helpers ----------------
__device__ __forceinline__ uint32_t smem_u32(const void* p) {
    uint32_t a;
    asm("{ .reg .u64 t; cvta.to.shared.u64 t, %1; cvt.u32.u64 %0, t; }" : "=r"(a) : "l"(p));
    return a;
}
__device__ __forceinline__ void cpa16(uint32_t dst, const void* src) {
    asm volatile("cp.async.cg.shared.global [%0], [%1], 16;" :: "r"(dst), "l"(src));
}
#define CP_COMMIT() asm volatile("cp.async.commit_group;" ::: "memory")
#define CP_WAIT(n)  asm volatile("cp.async.wait_group %0;" :: "n"(n) : "memory")

__device__ __forceinline__ void cp_bulk(uint32_t dst, const void* src, uint32_t bytes, uint32_t mbar) {
    asm volatile(
        "cp.async.bulk.shared::cluster.global.mbarrier::complete_tx::bytes [%0], [%1], %2, [%3];"
        :: "r"(dst), "l"(src), "r"(bytes), "r"(mbar) : "memory");
}
#define MBARRIER_INIT(addr, cnt) \
    asm volatile("mbarrier.init.shared.b64 [%0], %1;" :: "r"((uint32_t)(addr)), "r"((uint32_t)(cnt)) : "memory")
#define MBARRIER_EXPECT_TX(addr, tx) \
    asm volatile("mbarrier.arrive.expect_tx.shared.b64 _, [%0], %1;" :: "r"((uint32_t)(addr)), "r"((uint32_t)(tx)) : "memory")
#define MBARRIER_WAIT_PARITY(mbar_smem_addr, phase_parity) do { \
    uint32_t _mbar = (uint32_t)(mbar_smem_addr); \
    uint32_t _parity = (uint32_t)(phase_parity); \
    uint32_t _done; \
    asm volatile( \
        "{\n\t.reg .pred p;\n\t" \
        "mbarrier.try_wait.parity.acquire.cta.shared::cta.b64 p, [%1], %2;\n\t" \
        "selp.b32 %0, 1, 0, p;\n\t}" \
        : "=r"(_done) : "r"(_mbar), "r"(_parity) : "memory"); \
    if (!_done) { \
        asm volatile( \
            "{\n\t.reg .pred P1;\n\t" \
            "WAIT_LOOP_%=:\n\t" \
            "mbarrier.try_wait.parity.acquire.cta.shared::cta.b64 P1, [%0], %1, 0x989680;\n\t" \
            "@P1 bra.uni WAIT_DONE_%=;\n\t" \
            "bra.uni WAIT_LOOP_%=;\n\t" \
            "WAIT_DONE_%=:\n\t}" \
            :: "r"(_mbar), "r"(_parity) : "memory"); \
    } \
} while(0)

#define LDSM4(r0,r1,r2,r3,a) \
    asm volatile("ldmatrix.sync.aligned.m8n8.x4.shared.b16 {%0,%1,%2,%3}, [%4];" \
                 : "=r"(r0),"=r"(r1),"=r"(r2),"=r"(r3) : "r"(a))

__device__ __forceinline__ void mma_f16(float* c, const unsigned* a, const unsigned* b) {
    asm volatile(
        "mma.sync.aligned.m16n8k16.row.col.f32.f16.f16.f32 "
        "{%0,%1,%2,%3}, {%4,%5,%6,%7}, {%8,%9}, {%0,%1,%2,%3};"
        : "+f"(c[0]), "+f"(c[1]), "+f"(c[2]), "+f"(c[3])
        : "r"(a[0]), "r"(a[1]), "r"(a[2]), "r"(a[3]), "r"(b[0]), "r"(b[1]));
}

// fast sigmoid / tanh (overflow-safe, ~1e-6 rel err)
__device__ __forceinline__ float fsig(float x) {
    return __fdividef(1.f, 1.f + __expf(-x));
}
__device__ __forceinline__ float ftanh(float x) {
    return 1.f - 2.f * __fdividef(1.f, __expf(2.f * x) + 1.f);
}

// -------- quad weight f32 -> f16 + index-dtype detect (ONE launch) --------
__global__ __launch_bounds__(256) void h_conv4d(
    const float* __restrict__ inA, const float* __restrict__ inB,
    const float* __restrict__ inC, const float* __restrict__ inD,
    __half* __restrict__ outA, __half* __restrict__ outB,
    __half* __restrict__ outC, __half* __restrict__ outD, int n,
    const int* __restrict__ idx, int nidx)
{
    int i = blockIdx.x * 256 + threadIdx.x;
    if      (i < n)     outA[i]         = __float2half_rn(inA[i]);
    else if (i < 2 * n) outB[i - n]     = __float2half_rn(inB[i - n]);
    else if (i < 3 * n) outC[i - 2 * n] = __float2half_rn(inC[i - 2 * n]);
    else if (i < 4 * n) outD[i - 3 * n] = __float2half_rn(inD[i - 3 * n]);
    if (blockIdx.x == 0) {
        __shared__ int any;
        if (threadIdx.x == 0) any = 0;
        __syncthreads();
        int loc = 0;
        for (int k = threadIdx.x; k < nidx / 2; k += 256) loc |= idx[2 * k + 1];
        if (loc) atomicOr(&any, 1);
        __syncthreads();
        if (threadIdx.x == 0) g_idx_stride = any ? 1 : 2;
    }
}

// ------------- embedding concat + fused block-0 ln1 -------------
__global__ __launch_bounds__(128) void embed_ln_kernel(
    const float* __restrict__ gs,
    const int* __restrict__ stage, const int* __restrict__ egoc,
    const int* __restrict__ oppc,  const int* __restrict__ egoa,
    const int* __restrict__ oppa,
    const float* __restrict__ e_stage, const float* __restrict__ e_char,
    const float* __restrict__ e_act,
    const float* __restrict__ lg, const float* __restrict__ lb)
{
    int bi = blockIdx.x;
    int t = bi >> 8, b = bi & 255;
    int ip = (b * T_STEPS + t) * g_idx_stride;
    int s_  = stage[ip], ec = egoc[ip], oc = oppc[ip], ea = egoa[ip], oa = oppa[ip];
    int c = threadIdx.x * 4;
    float4 v;
    if      (c < 64)  v = *reinterpret_cast<const float4*>(e_stage + s_ * 64  + c);
    else if (c < 128) v = *reinterpret_cast<const float4*>(e_char  + ec * 64  + (c - 64));
    else if (c < 192) v = *reinterpret_cast<const float4*>(e_char  + oc * 64  + (c - 128));
    else if (c < 320) v = *reinterpret_cast<const float4*>(e_act   + ea * 128 + (c - 192));
    else if (c < 448) v = *reinterpret_cast<const float4*>(e_act   + oa * 128 + (c - 320));
    else              v = *reinterpret_cast<const float4*>(gs + (size_t)(b * T_STEPS + t) * 64 + (c - 448));
    *reinterpret_cast<float4*>(d_X + (size_t)bi * HH + c) = v;

    float s = v.x + v.y + v.z + v.w;
    float sq = v.x*v.x + v.y*v.y + v.z*v.z + v.w*v.w;
#pragma unroll
    for (int off = 16; off; off >>= 1) {
        s  += __shfl_xor_sync(0xffffffffu, s,  off);
        sq += __shfl_xor_sync(0xffffffffu, sq, off);
    }
    __shared__ float ss[4], sqs[4];
    int wid = threadIdx.x >> 5, lane = threadIdx.x & 31;
    if (lane == 0) { ss[wid] = s; sqs[wid] = sq; }
    __syncthreads();
    s  = ss[0] + ss[1] + ss[2] + ss[3];
    sq = sqs[0] + sqs[1] + sqs[2] + sqs[3];
    float mean = s * (1.f / HH);
    float var  = sq * (1.f / HH) - mean * mean;
    float inv  = rsqrtf(var + 1e-5f);
    float4 gg = *reinterpret_cast<const float4*>(lg + c);
    float4 bb = *reinterpret_cast<const float4*>(lb + c);
    __half2 p0 = __floats2half2_rn((v.x - mean) * inv * gg.x + bb.x,
                                   (v.y - mean) * inv * gg.y + bb.y);
    __half2 p1 = __floats2half2_rn((v.z - mean) * inv * gg.z + bb.z,
                                   (v.w - mean) * inv * gg.w + bb.w);
    __half* yr = d_XN + (size_t)bi * HH + c;
    *reinterpret_cast<__half2*>(yr)     = p0;
    *reinterpret_cast<__half2*>(yr + 2) = p1;
}

// ---------------- layernorm: fp32 in, half out ----------------
__global__ __launch_bounds__(256) void ln_kernel(
    const float* __restrict__ x, __half* __restrict__ y,
    const float* __restrict__ g, const float* __restrict__ b, int nrows)
{
    int warp = (blockIdx.x * blockDim.x + threadIdx.x) >> 5;
    if (warp >= nrows) return;
    int lane = threadIdx.x & 31;
    const float* xr = x + (size_t)warp * HH;
    float4 v[4];
    float s = 0.f, sq = 0.f;
#pragma unroll
    for (int i = 0; i < 4; i++) {
        v[i] = *reinterpret_cast<const float4*>(xr + (i * 32 + lane) * 4);
        s  += v[i].x + v[i].y + v[i].z + v[i].w;
        sq += v[i].x*v[i].x + v[i].y*v[i].y + v[i].z*v[i].z + v[i].w*v[i].w;
    }
#pragma unroll
    for (int off = 16; off; off >>= 1) {
        s  += __shfl_xor_sync(0xffffffffu, s,  off);
        sq += __shfl_xor_sync(0xffffffffu, sq, off);
    }
    float mean = s * (1.f / HH);
    float var  = sq * (1.f / HH) - mean * mean;
    float inv  = rsqrtf(var + 1e-5f);
    __half* yr = y + (size_t)warp * HH;
#pragma unroll
    for (int i = 0; i < 4; i++) {
        int c = (i * 32 + lane) * 4;
        float4 gg = *reinterpret_cast<const float4*>(g + c);
        float4 bb = *reinterpret_cast<const float4*>(b + c);
        __half2 p0 = __floats2half2_rn((v[i].x - mean) * inv * gg.x + bb.x,
                                       (v[i].y - mean) * inv * gg.y + bb.y);
        __half2 p1 = __floats2half2_rn((v[i].z - mean) * inv * gg.z + bb.z,
                                       (v[i].w - mean) * inv * gg.w + bb.w);
        *reinterpret_cast<__half2*>(yr + c)     = p0;
        *reinterpret_cast<__half2*>(yr + c + 2) = p1;
    }
}

// == fp16 TC GEMM v6: 128x128 tile, KC=64, cp.async.bulk row loads (1/thread),
//    row stride 144B (bank-permuted, no XOR), per-stage mbarrier, 2 CTA/SM ==
#define KC 64
#define G_RP 144                 // bytes per row in smem stage
#define G_STG (128*G_RP)         // 18432 bytes per stage per operand
#define GEMM_SMEM (6*G_STG)      // 110592

template <int MODE>
__global__ __launch_bounds__(256, 2) void gemm_h(
    const __half* __restrict__ A, const __half* __restrict__ W,
    void* __restrict__ Cv, int N, int K,
    const float* __restrict__ bias, const float* __restrict__ bias2,
    const float* __restrict__ res)
{
    extern __shared__ __align__(128) char sm[];
    __shared__ __align__(8) uint64_t mbars[3];
    const uint32_t abase = smem_u32(sm);
    const uint32_t bbase = abase + 3 * G_STG;
    const uint32_t mb = smem_u32(mbars);

    const int tid = threadIdx.x;
    const int wid = tid >> 5, lane = tid & 31;
    const int wm = wid & 1, wn = wid >> 1;
    const int g = lane >> 2, tq = lane & 3;
    const int m0 = blockIdx.y * 128, n0 = blockIdx.x * 128;

    if (tid < 3) MBARRIER_INIT(mb + tid * 8, 1);
    __syncthreads();

    float acc[4][4][4];
#pragma unroll
    for (int i = 0; i < 4; i++)
#pragma unroll
        for (int j = 0; j < 4; j++)
#pragma unroll
            for (int q = 0; q < 4; q++) acc[i][j][q] = 0.f;

    // loader: thread -> one 128B row copy; opr 0 = A, 1 = B
    const int opr = tid >> 7;
    const int lr = tid & 127;
    const __half* srow = (opr ? (W + (size_t)(n0 + lr) * K)
                              : (A + (size_t)(m0 + lr) * K));
    const uint32_t dbase = (opr ? bbase : abase) + lr * G_RP;

    auto issue = [&](int buf, int ch) {
        if (tid == 0) MBARRIER_EXPECT_TX(mb + buf * 8, 32768u);
        cp_bulk(dbase + buf * G_STG, srow + ch * KC, 128u, mb + buf * 8);
    };

    const int nst = K / KC;
    issue(0, 0);
    issue(1, 1);
    for (int s = 0; s < nst; s++) {
        const int buf = s % 3;
        MBARRIER_WAIT_PARITY(mb + buf * 8, (s / 3) & 1);
        __syncthreads();
        if (s + 2 < nst) issue((s + 2) % 3, s + 2);
#pragma unroll
        for (int ks = 0; ks < 4; ks++) {
            const int q = ks * 2 + (lane >> 4);
            unsigned af[4][4], bf[4][2];
#pragma unroll
            for (int ms = 0; ms < 4; ms++) {
                const int ar = wm * 64 + ms * 16 + (lane & 15);
                uint32_t ad = abase + buf * G_STG + (uint32_t)(ar * G_RP + q * 16);
                LDSM4(af[ms][0], af[ms][1], af[ms][2], af[ms][3], ad);
            }
#pragma unroll
            for (int nb = 0; nb < 2; nb++) {
                const int br = wn * 32 + nb * 16 + (lane & 15);
                uint32_t bd = bbase + buf * G_STG + (uint32_t)(br * G_RP + q * 16);
                unsigned r0, r1, r2, r3;
                LDSM4(r0, r1, r2, r3, bd);
                bf[2 * nb][0] = r0; bf[2 * nb][1] = r2;
                bf[2 * nb + 1][0] = r1; bf[2 * nb + 1][1] = r3;
            }
#pragma unroll
            for (int ms = 0; ms < 4; ms++)
#pragma unroll
                for (int ns = 0; ns < 4; ns++)
                    mma_f16(acc[ms][ns], af[ms], bf[ns]);
        }
    }

    float* Cf = reinterpret_cast<float*>(Cv);
    __half* Ch = reinterpret_cast<__half*>(Cv);
#pragma unroll
    for (int ms = 0; ms < 4; ms++) {
#pragma unroll
        for (int ns = 0; ns < 4; ns++) {
            const int col = n0 + wn * 32 + ns * 8 + tq * 2;
            const float b0 = bias[col], b1 = bias[col + 1];
#pragma unroll
            for (int half = 0; half < 2; half++) {
                const int row = m0 + wm * 64 + ms * 16 + g + half * 8;
                float v0 = acc[ms][ns][half * 2 + 0] + b0;
                float v1 = acc[ms][ns][half * 2 + 1] + b1;
                if (MODE == 0) {
                    v0 += bias2[col]; v1 += bias2[col + 1];
                    *reinterpret_cast<__half2*>(Ch + (size_t)row * N + col) =
                        __floats2half2_rn(v0, v1);
                } else if (MODE == 1) {
                    v0 = 0.5f * v0 * (1.f + erff(v0 * 0.7071067811865475f));
                    v1 = 0.5f * v1 * (1.f + erff(v1 * 0.7071067811865475f));
                    *reinterpret_cast<__half2*>(Ch + (size_t)row * N + col) =
                        __floats2half2_rn(v0, v1);
                } else {
                    const float2 rr = *reinterpret_cast<const float2*>(res + (size_t)row * N + col);
                    v0 += rr.x; v1 += rr.y;
                    *reinterpret_cast<float2*>(Cf + (size_t)row * N + col) = make_float2(v0, v1);
                }
            }
        }
    }
}

// ---- persistent recurrent (512 threads, 16 warps): W resident, chunked TMA H ----
// h global layout per rt-group: 4 chunks of 16KB (column groups of 128):
//   off = rt*32768 + cg*8192 + b*128 + ((q ^ (b&7))<<3) + (j&7)  [halves]
// smem: W [16][64][40] (81920) | H 4x[64][128] (65536) | Gin (8192)
//       | gt [64][65] f32 (16640) | mbar[4] (32)
#define R_WOFF 0
#define R_HOFF 81920
#define R_GIOFF (81920 + 65536)
#define R_GOFF (R_GIOFF + 8192)
#define R_MBAR (R_GOFF + 64*65*4)
#define REC_SMEM (R_MBAR + 32)

__global__ __launch_bounds__(512) void lstm_rec_h(
    const __half* __restrict__ Whh, const __half* __restrict__ G,
    const float* __restrict__ X, float* __restrict__ Y,
    __half* __restrict__ h0, __half* __restrict__ h1, unsigned* bar)
{
    extern __shared__ __align__(128) char rsm[];
    const uint32_t ws0 = smem_u32(rsm) + R_WOFF;
    const uint32_t hs0 = smem_u32(rsm) + R_HOFF;
    const uint32_t gi0 = smem_u32(rsm) + R_GIOFF;
    const uint32_t mb  = smem_u32(rsm) + R_MBAR;
    __half* Gin = reinterpret_cast<__half*>(rsm + R_GIOFF);
    float (*gt)[65] = reinterpret_cast<float(*)[65]>(rsm + R_GOFF);

    const int rt = blockIdx.x >> 5;
    const int ct = blockIdx.x & 31;
    const int tid = threadIdx.x;
    const int wid = tid >> 5, lane = tid & 31;
    const int wm = wid >> 2, wn = wid & 3;      // 4 m-tiles x 4 gates
    const int g = lane >> 2, tq = lane & 3;

    // one-time W load (40-pad layout): 4096 tasks over 512 threads
#pragma unroll
    for (int i = 0; i < 8; i++) {
        int u = tid + i * 512;
        int c = u >> 8, rem = u & 255;
        int r = rem >> 2, q = rem & 3;
        const __half* src = Whh + (size_t)((r >> 4) * 512 + ct * 16 + (r & 15)) * HH
                            + c * 32 + q * 8;
        cpa16(ws0 + (uint32_t)(((c * 64 + r) * 40 + q * 8) * 2), src);
    }
    CP_COMMIT();
    if (tid < 4) MBARRIER_INIT(mb + tid * 8, 1);
    CP_WAIT(0);
    __syncthreads();

    float creg[2] = {0.f, 0.f};

    for (int t = 0; t < T_STEPS; t++) {
        const __half* hin  = (t & 1) ? h1 : h0;
        __half*       hout = (t & 1) ? h0 : h1;
        const __half* Gt = G + (size_t)t * BB * H4;

        // 4 chunked bulk copies (16KB each), independent mbarriers
        if (tid == 0) {
#pragma unroll
            for (int cg = 0; cg < 4; cg++) {
                MBARRIER_EXPECT_TX(mb + cg * 8, 16384u);
                cp_bulk(hs0 + cg * 16384, hin + (size_t)rt * 32768 + cg * 8192,
                        16384u, mb + cg * 8);
            }
        }
        // Gin prefetch: 512 tasks, 1/thread (overlaps MMA)
        {
            int r = tid >> 3, seg = tid & 7;
            int gate = seg >> 1, hq = seg & 1;
            cpa16(gi0 + (uint32_t)((r * 64 + gate * 16 + hq * 8) * 2),
                  Gt + (size_t)(rt * 64 + r) * H4 + gate * 512 + ct * 16 + hq * 8);
        }
        CP_COMMIT();

        // prefetch X (h-independent)
        float xv[2];
#pragma unroll
        for (int it = 0; it < 2; it++) {
            const int e = it * 512 + tid;
            const int gb = rt * 64 + (e >> 4);
            const int j = ct * 16 + (e & 15);
            xv[it] = __ldg(X + (size_t)t * BB * HH + (size_t)gb * HH + j);
        }

        float acc[2][4];
#pragma unroll
        for (int j = 0; j < 2; j++)
#pragma unroll
            for (int q = 0; q < 4; q++) acc[j][q] = 0.f;

        // 16 K-chunks; wait per 4-chunk group (pipelined TMA)
        for (int s = 0; s < 16; s++) {
            if ((s & 3) == 0) MBARRIER_WAIT_PARITY(mb + (s >> 2) * 8, t & 1);
#pragma unroll
            for (int ks = 0; ks < 2; ks++) {
                const int kc = ks * 16 + ((lane >> 4) << 3);
                const int ql = (s & 3) * 4 + (kc >> 3);   // local 16B segment 0..15
                unsigned af[4], bf[2][2];
                {
                    const int ar = wm * 16 + (lane & 15);
                    uint32_t ad = hs0 + (s >> 2) * 16384 +
                                  (uint32_t)(ar * 256 + ((ql ^ (ar & 7)) << 4));
                    LDSM4(af[0], af[1], af[2], af[3], ad);
                }
                {
                    const int br = wn * 16 + (lane & 15);
                    uint32_t bd = ws0 + (uint32_t)(((s * 64 + br) * 40 + kc) * 2);
                    unsigned r0, r1, r2, r3;
                    LDSM4(r0, r1, r2, r3, bd);
                    bf[0][0] = r0; bf[0][1] = r2;
                    bf[1][0] = r1; bf[1][1] = r3;
                }
                mma_f16(acc[0], af, bf[0]);
                mma_f16(acc[1], af, bf[1]);
            }
        }

        CP_WAIT(0);          // Gin ready
        __syncthreads();     // protects gt reuse from previous step

        // gates = acc + Gin -> smem exchange tile (warp (wm,wn): rows wm*16..+16, gate wn)
#pragma unroll
        for (int ns = 0; ns < 2; ns++) {
            const int ncol = ns * 8 + tq * 2;
#pragma unroll
            for (int half = 0; half < 2; half++) {
                const int row = wm * 16 + g + half * 8;
                const __half2 gh = *reinterpret_cast<const __half2*>(
                    Gin + row * 64 + wn * 16 + ncol);
                const float2 gi = __half22float2(gh);
                gt[row][wn * 16 + ncol]     = acc[ns][half * 2 + 0] + gi.x;
                gt[row][wn * 16 + ncol + 1] = acc[ns][half * 2 + 1] + gi.y;
            }
        }
        __syncthreads();

        // cell update (fast-math), h stored chunked+swizzled; 2 elems/thread
        float hnv[2];
#pragma unroll
        for (int it = 0; it < 2; it++) {
            const int e = it * 512 + tid;
            const int b = e >> 4;
            const int jl = e & 15;
            const float ig = gt[b][jl];
            const float fg = gt[b][16 + jl];
            const float gg = gt[b][32 + jl];
            const float og = gt[b][48 + jl];
            const float cn = fsig(fg) * creg[it] + fsig(ig) * ftanh(gg);
            const float hn = fsig(og) * ftanh(cn);
            creg[it] = cn;
            hnv[it] = hn;
            const int j = ct * 16 + jl;
            const int cg = j >> 7;
            const int q = (j & 127) >> 3;
            const size_t hoff = (size_t)rt * 32768 + cg * 8192 + b * 128 +
                                ((q ^ (b & 7)) << 3) + (jl & 7);
            const __half hh = __float2half_rn(hn);
            asm volatile("st.global.cg.b16 [%0], %1;"
                         :: "l"(hout + hoff), "h"(__half_as_ushort(hh)));
        }
        // arrive (h published), Y writes off the critical path, then wait
        __syncthreads();
        if (tid == 0) {
            __threadfence();
            atomicAdd(bar + rt, 1u);
        }
#pragma unroll
        for (int it = 0; it < 2; it++) {
            const int e = it * 512 + tid;
            const int gb = rt * 64 + (e >> 4);
            const int j = ct * 16 + (e & 15);
            Y[(size_t)t * BB * HH + (size_t)gb * HH + j] = xv[it] + hnv[it];
        }
        if (tid == 0) {
            const unsigned target = (unsigned)(t + 1) * 32u;
            while (*reinterpret_cast<volatile unsigned*>(bar + rt) < target) __nanosleep(32);
            __threadfence();
        }
        __syncthreads();
    }
}

// ---------------- output heads ----------------
__global__ __launch_bounds__(256) void heads_kernel(
    const float* __restrict__ last,
    const float* __restrict__ btn_w, const float* __restrict__ btn_b,
    const float* __restrict__ ms_w,  const float* __restrict__ ms_b,
    const float* __restrict__ cs_w,  const float* __restrict__ cs_b,
    float* __restrict__ out)
{
    int b = blockIdx.x;
    __shared__ float row[HH];
    for (int i = threadIdx.x; i < HH; i += blockDim.x) row[i] = last[(size_t)b * HH + i];
    __syncthreads();
    int warp = threadIdx.x >> 5, lane = threadIdx.x & 31;
    for (int o = warp; o < 58; o += 8) {
        const float* w; float bias; float* dst;
        if (o < 16)      { w = btn_w + o * HH;        bias = btn_b[o];      dst = out + b * 16 + o; }
        else if (o < 37) { int oo = o - 16; w = ms_w + oo * HH; bias = ms_b[oo]; dst = out + 4096 + b * 21 + oo; }
        else             { int oo = o - 37; w = cs_w + oo * HH; bias = cs_b[oo]; dst = out + 9472 + b * 21 + oo; }
        float s = 0.f;
        for (int k = lane; k < HH; k += 32) s += row[k] * w[k];
#pragma unroll
        for (int off = 16; off; off >>= 1) s += __shfl_down_sync(0xffffffffu, s, off);
        if (lane == 0) *dst = s + bias;
    }
}

// ---------------- launch ----------------
extern "C" void kernel_launch(void* const* d_in, const int* in_sizes, int n_in,
                              void* d_out, int out_size)
{
    const float* gamestate = (const float*)d_in[0];
    const int*   stage     = (const int*)d_in[1];
    const int*   egoc      = (const int*)d_in[2];
    const int*   oppc      = (const int*)d_in[3];
    const int*   egoa      = (const int*)d_in[4];
    const int*   oppa      = (const int*)d_in[5];
    const float* emb_stage = (const float*)d_in[6];
    const float* emb_char  = (const float*)d_in[7];
    const float* emb_act   = (const float*)d_in[8];
    const float* ln1_g     = (const float*)d_in[9];
    const float* ln1_b     = (const float*)d_in[10];
    const float* w_ih      = (const float*)d_in[11];
    const float* w_hh      = (const float*)d_in[12];
    const float* b_ih      = (const float*)d_in[13];
    const float* b_hh      = (const float*)d_in[14];
    const float* ln2_g     = (const float*)d_in[15];
    const float* ln2_b     = (const float*)d_in[16];
    const float* fc_w      = (const float*)d_in[17];
    const float* fc_b      = (const float*)d_in[18];
    const float* proj_w    = (const float*)d_in[19];
    const float* proj_b    = (const float*)d_in[20];
    const float* btn_w     = (const float*)d_in[21];
    const float* btn_b     = (const float*)d_in[22];
    const float* ms_w      = (const float*)d_in[23];
    const float* ms_b      = (const float*)d_in[24];
    const float* cs_w      = (const float*)d_in[25];
    const float* cs_b      = (const float*)d_in[26];

    void *pX, *pXN, *pY, *pYN, *pG, *pFC, *ph0, *ph1, *pbar, *pWih, *pWfc, *pWpr, *pWhh;
    cudaGetSymbolAddress(&pX,  d_X);
    cudaGetSymbolAddress(&pXN, d_XN);
    cudaGetSymbolAddress(&pY,  d_Y);
    cudaGetSymbolAddress(&pYN, d_YN);
    cudaGetSymbolAddress(&pG,  d_G);
    cudaGetSymbolAddress(&pFC, d_FC);
    cudaGetSymbolAddress(&ph0, d_h0);
    cudaGetSymbolAddress(&ph1, d_h1);
    cudaGetSymbolAddress(&pbar, d_bar);
    cudaGetSymbolAddress(&pWih, d_Wih);
    cudaGetSymbolAddress(&pWfc, d_Wfc);
    cudaGetSymbolAddress(&pWpr, d_Wpr);
    cudaGetSymbolAddress(&pWhh, d_Whh);
    float*  X  = (float*)pX;   __half* XN = (__half*)pXN;
    float*  Y  = (float*)pY;   __half* YN = (__half*)pYN;
    __half* G  = (__half*)pG;  __half* FC = (__half*)pFC;
    __half* h0 = (__half*)ph0; __half* h1 = (__half*)ph1;
    __half* Wih = (__half*)pWih; __half* Wfc = (__half*)pWfc;
    __half* Wpr = (__half*)pWpr; __half* Whh = (__half*)pWhh;
    unsigned* bar = (unsigned*)pbar;

    cudaFuncSetAttribute(gemm_h<0>, cudaFuncAttributeMaxDynamicSharedMemorySize, GEMM_SMEM);
    cudaFuncSetAttribute(gemm_h<1>, cudaFuncAttributeMaxDynamicSharedMemorySize, GEMM_SMEM);
    cudaFuncSetAttribute(gemm_h<2>, cudaFuncAttributeMaxDynamicSharedMemorySize, GEMM_SMEM);
    cudaFuncSetAttribute(lstm_rec_h, cudaFuncAttributeMaxDynamicSharedMemorySize, REC_SMEM);

    const int M = T_STEPS * BB;        // 65536
    const int WN = NBLK * H4 * HH;     // 4M

    // launch order: conv+detect(1), embed_ln(2), gemm<0>(3), lstm(4 = ncu slot)
    h_conv4d<<<4 * WN / 256, 256>>>(w_ih, fc_w, proj_w, w_hh, Wih, Wfc, Wpr, Whh, WN,
                                    stage, BB * T_STEPS);
    embed_ln_kernel<<<M, 128>>>(gamestate, stage, egoc, oppc, egoa, oppa,
                                emb_stage, emb_char, emb_act, ln1_g, ln1_b);

    for (int i = 0; i < NBLK; i++) {
        if (i > 0)
            ln_kernel<<<M / 8, 256>>>(X, XN, ln1_g + i * HH, ln1_b + i * HH, M);
        gemm_h<0><<<dim3(H4 / 128, M / 128), 256, GEMM_SMEM>>>(
            XN, Wih + (size_t)i * H4 * HH, G, H4, HH,
            b_ih + i * H4, b_hh + i * H4, nullptr);

        cudaMemsetAsync(h0, 0, BB * HH * sizeof(__half), 0);
        cudaMemsetAsync(bar, 0, 4 * sizeof(unsigned), 0);
        lstm_rec_h<<<128, 512, REC_SMEM>>>(Whh + (size_t)i * H4 * HH, G, X, Y, h0, h1, bar);

        ln_kernel<<<M / 8, 256>>>(Y, YN, ln2_g + i * HH, ln2_b + i * HH, M);
        gemm_h<1><<<dim3(H4 / 128, M / 128), 256, GEMM_SMEM>>>(
            YN, Wfc + (size_t)i * H4 * HH, FC, H4, HH,
            fc_b + i * H4, nullptr, nullptr);
        gemm_h<2><<<dim3(HH / 128, M / 128), 256, GEMM_SMEM>>>(
            FC, Wpr + (size_t)i * HH * H4, X, HH, H4,
            proj_b + i * HH, nullptr, Y);
    }

    heads_kernel<<<BB, 256>>>(X + (size_t)(T_STEPS - 1) * BB * HH,
                              btn_w, btn_b, ms_w, ms_b, cs_w, cs_b,
                              (float*)d_out);
}

// round 14
// speedup vs baseline: 1.2475x; 1.2475x over previous
#include <cuda_runtime.h>
#include <cuda_fp16.h>
#include <cstdint>
#include <math.h>

#define T_STEPS 256
#define BB      256
#define HH      512
#define H4      2048
#define NBLK    4

// ---------------- static device scratch ----------------
// XNp/YNp/FCp and the weight buffers hold a PACKED+SWIZZLED layout:
// element (row n, col k) of an [Nrows, K] matrix lives at
//   ((n>>7)*(K/64) + (k>>6))*8192 + (n&127)*64 + ((((k&63)>>3) ^ (n&7))<<3) + (k&7)
// i.e. contiguous 16KB blocks of (128 rows x 64 cols), rows of 128B, XOR-swizzled
// 16B segments -> one cp.async.bulk per GEMM stage operand + conflict-free ldmatrix.
__device__ float  d_X [T_STEPS*BB*HH];
__device__ __half d_XN[T_STEPS*BB*HH];           // packed (K=512)
__device__ float  d_Y [T_STEPS*BB*HH];
__device__ __half d_YN[T_STEPS*BB*HH];           // packed (K=512)
__device__ __half d_G [(size_t)T_STEPS*BB*H4];   // normal layout (recurrent reads it)
__device__ __half d_FC[(size_t)T_STEPS*BB*H4];   // packed (K=2048)
__device__ __half d_h0[BB*HH];                   // recurrent chunked+swizzled layout
__device__ __half d_h1[BB*HH];
__device__ __half d_Wih [NBLK*H4*HH];            // packed (K=512)
__device__ __half d_Wfc [NBLK*H4*HH];            // packed (K=512)
__device__ __half d_Wpr [NBLK*HH*H4];            // packed (K=2048)
__device__ __half d_Whh [NBLK*H4*HH];            // LINEAR (recurrent W loader)
__device__ unsigned d_bar[4];
__device__ int g_idx_stride;

// ---------------- ptx helpers ----------------
__device__ __forceinline__ uint32_t smem_u32(const void* p) {
    uint32_t a;
    asm("{ .reg .u64 t; cvta.to.shared.u64 t, %1; cvt.u32.u64 %0, t; }" : "=r"(a) : "l"(p));
    return a;
}
__device__ __forceinline__ void cpa16(uint32_t dst, const void* src) {
    asm volatile("cp.async.cg.shared.global [%0], [%1], 16;" :: "r"(dst), "l"(src));
}
#define CP_COMMIT() asm volatile("cp.async.commit_group;" ::: "memory")
#define CP_WAIT(n)  asm volatile("cp.async.wait_group %0;" :: "n"(n) : "memory")

__device__ __forceinline__ void cp_bulk(uint32_t dst, const void* src, uint32_t bytes, uint32_t mbar) {
    asm volatile(
        "cp.async.bulk.shared::cluster.global.mbarrier::complete_tx::bytes [%0], [%1], %2, [%3];"
        :: "r"(dst), "l"(src), "r"(bytes), "r"(mbar) : "memory");
}
#define MBARRIER_INIT(addr, cnt) \
    asm volatile("mbarrier.init.shared.b64 [%0], %1;" :: "r"((uint32_t)(addr)), "r"((uint32_t)(cnt)) : "memory")
#define MBARRIER_EXPECT_TX(addr, tx) \
    asm volatile("mbarrier.arrive.expect_tx.shared.b64 _, [%0], %1;" :: "r"((uint32_t)(addr)), "r"((uint32_t)(tx)) : "memory")
#define MBARRIER_WAIT_PARITY(mbar_smem_addr, phase_parity) do { \
    uint32_t _mbar = (uint32_t)(mbar_smem_addr); \
    uint32_t _parity = (uint32_t)(phase_parity); \
    uint32_t _done; \
    asm volatile( \
        "{\n\t.reg .pred p;\n\t" \
        "mbarrier.try_wait.parity.acquire.cta.shared::cta.b64 p, [%1], %2;\n\t" \
        "selp.b32 %0, 1, 0, p;\n\t}" \
        : "=r"(_done) : "r"(_mbar), "r"(_parity) : "memory"); \
    if (!_done) { \
        asm volatile( \
            "{\n\t.reg .pred P1;\n\t" \
            "WAIT_LOOP_%=:\n\t" \
            "mbarrier.try_wait.parity.acquire.cta.shared::cta.b64 P1, [%0], %1, 0x989680;\n\t" \
            "@P1 bra.uni WAIT_DONE_%=;\n\t" \
            "bra.uni WAIT_LOOP_%=;\n\t" \
            "WAIT_DONE_%=:\n\t}" \
            :: "r"(_mbar), "r"(_parity) : "memory"); \
    } \
} while(0)

#define LDSM4(r0,r1,r2,r3,a) \
    asm volatile("ldmatrix.sync.aligned.m8n8.x4.shared.b16 {%0,%1,%2,%3}, [%4];" \
                 : "=r"(r0),"=r"(r1),"=r"(r2),"=r"(r3) : "r"(a))

__device__ __forceinline__ void mma_f16(float* c, const unsigned* a, const unsigned* b) {
    asm volatile(
        "mma.sync.aligned.m16n8k16.row.col.f32.f16.f16.f32 "
        "{%0,%1,%2,%3}, {%4,%5,%6,%7}, {%8,%9}, {%0,%1,%2,%3};"
        : "+f"(c[0]), "+f"(c[1]), "+f"(c[2]), "+f"(c[3])
        : "r"(a[0]), "r"(a[1]), "r"(a[2]), "r"(a[3]), "r"(b[0]), "r"(b[1]));
}

__device__ __forceinline__ float fsig(float x) {
    return __fdividef(1.f, 1.f + __expf(-x));
}
__device__ __forceinline__ float ftanh(float x) {
    return 1.f - 2.f * __fdividef(1.f, __expf(2.f * x) + 1.f);
}

// packed index helper (halves) for [*, K] matrix
__device__ __forceinline__ size_t pk_idx(int n, int k, int K) {
    return ((size_t)(n >> 7) * (K >> 6) + (k >> 6)) * 8192 + (n & 127) * 64 +
           ((((k & 63) >> 3) ^ (n & 7)) << 3) + (k & 7);
}

// -------- weight f32 -> f16 pack (A,B,C packed; D linear) + idx detect --------
__global__ __launch_bounds__(256) void h_conv4d(
    const float* __restrict__ inA, const float* __restrict__ inB,
    const float* __restrict__ inC, const float* __restrict__ inD,
    __half* __restrict__ outA, __half* __restrict__ outB,
    __half* __restrict__ outC, __half* __restrict__ outD, int n,
    const int* __restrict__ idx, int nidx)
{
    int i = blockIdx.x * 256 + threadIdx.x;
    if (i < n) {                                   // w_ih: per-block [2048,512]
        int blk = i / (H4 * HH), rem = i % (H4 * HH);
        int r = rem / HH, k = rem % HH;
        outA[(size_t)blk * H4 * HH + pk_idx(r, k, HH)] = __float2half_rn(inA[i]);
    } else if (i < 2 * n) {                        // fc_w: per-block [2048,512]
        int j = i - n;
        int blk = j / (H4 * HH), rem = j % (H4 * HH);
        int r = rem / HH, k = rem % HH;
        outB[(size_t)blk * H4 * HH + pk_idx(r, k, HH)] = __float2half_rn(inB[j]);
    } else if (i < 3 * n) {                        // proj_w: per-block [512,2048]
        int j = i - 2 * n;
        int blk = j / (HH * H4), rem = j % (HH * H4);
        int r = rem / H4, k = rem % H4;
        outC[(size_t)blk * HH * H4 + pk_idx(r, k, H4)] = __float2half_rn(inC[j]);
    } else if (i < 4 * n) {
        outD[i - 3 * n] = __float2half_rn(inD[i - 3 * n]);   // w_hh linear
    }
    if (blockIdx.x == 0) {
        __shared__ int any;
        if (threadIdx.x == 0) any = 0;
        __syncthreads();
        int loc = 0;
        for (int k = threadIdx.x; k < nidx / 2; k += 256) loc |= idx[2 * k + 1];
        if (loc) atomicOr(&any, 1);
        __syncthreads();
        if (threadIdx.x == 0) g_idx_stride = any ? 1 : 2;
    }
}

// ------------- embedding concat + fused block-0 ln1 (XN packed) -------------
__global__ __launch_bounds__(128) void embed_ln_kernel(
    const float* __restrict__ gs,
    const int* __restrict__ stage, const int* __restrict__ egoc,
    const int* __restrict__ oppc,  const int* __restrict__ egoa,
    const int* __restrict__ oppa,
    const float* __restrict__ e_stage, const float* __restrict__ e_char,
    const float* __restrict__ e_act,
    const float* __restrict__ lg, const float* __restrict__ lb)
{
    int bi = blockIdx.x;
    int t = bi >> 8, b = bi & 255;
    int ip = (b * T_STEPS + t) * g_idx_stride;
    int s_  = stage[ip], ec = egoc[ip], oc = oppc[ip], ea = egoa[ip], oa = oppa[ip];
    int c = threadIdx.x * 4;
    float4 v;
    if      (c < 64)  v = *reinterpret_cast<const float4*>(e_stage + s_ * 64  + c);
    else if (c < 128) v = *reinterpret_cast<const float4*>(e_char  + ec * 64  + (c - 64));
    else if (c < 192) v = *reinterpret_cast<const float4*>(e_char  + oc * 64  + (c - 128));
    else if (c < 320) v = *reinterpret_cast<const float4*>(e_act   + ea * 128 + (c - 192));
    else if (c < 448) v = *reinterpret_cast<const float4*>(e_act   + oa * 128 + (c - 320));
    else              v = *reinterpret_cast<const float4*>(gs + (size_t)(b * T_STEPS + t) * 64 + (c - 448));
    *reinterpret_cast<float4*>(d_X + (size_t)bi * HH + c) = v;

    float s = v.x + v.y + v.z + v.w;
    float sq = v.x*v.x + v.y*v.y + v.z*v.z + v.w*v.w;
#pragma unroll
    for (int off = 16; off; off >>= 1) {
        s  += __shfl_xor_sync(0xffffffffu, s,  off);
        sq += __shfl_xor_sync(0xffffffffu, sq, off);
    }
    __shared__ float ss[4], sqs[4];
    int wid = threadIdx.x >> 5, lane = threadIdx.x & 31;
    if (lane == 0) { ss[wid] = s; sqs[wid] = sq; }
    __syncthreads();
    s  = ss[0] + ss[1] + ss[2] + ss[3];
    sq = sqs[0] + sqs[1] + sqs[2] + sqs[3];
    float mean = s * (1.f / HH);
    float var  = sq * (1.f / HH) - mean * mean;
    float inv  = rsqrtf(var + 1e-5f);
    float4 gg = *reinterpret_cast<const float4*>(lg + c);
    float4 bb = *reinterpret_cast<const float4*>(lb + c);
    __half2 p0 = __floats2half2_rn((v.x - mean) * inv * gg.x + bb.x,
                                   (v.y - mean) * inv * gg.y + bb.y);
    __half2 p1 = __floats2half2_rn((v.z - mean) * inv * gg.z + bb.z,
                                   (v.w - mean) * inv * gg.w + bb.w);
    __half* yr = d_XN + pk_idx(bi, c, HH);
    *reinterpret_cast<__half2*>(yr)     = p0;
    *reinterpret_cast<__half2*>(yr + 2) = p1;
}

// ---------------- layernorm: fp32 in, packed half out ----------------
__global__ __launch_bounds__(256) void ln_kernel(
    const float* __restrict__ x, __half* __restrict__ y,
    const float* __restrict__ g, const float* __restrict__ b, int nrows)
{
    int warp = (blockIdx.x * blockDim.x + threadIdx.x) >> 5;
    if (warp >= nrows) return;
    int lane = threadIdx.x & 31;
    const float* xr = x + (size_t)warp * HH;
    float4 v[4];
    float s = 0.f, sq = 0.f;
#pragma unroll
    for (int i = 0; i < 4; i++) {
        v[i] = *reinterpret_cast<const float4*>(xr + (i * 32 + lane) * 4);
        s  += v[i].x + v[i].y + v[i].z + v[i].w;
        sq += v[i].x*v[i].x + v[i].y*v[i].y + v[i].z*v[i].z + v[i].w*v[i].w;
    }
#pragma unroll
    for (int off = 16; off; off >>= 1) {
        s  += __shfl_xor_sync(0xffffffffu, s,  off);
        sq += __shfl_xor_sync(0xffffffffu, sq, off);
    }
    float mean = s * (1.f / HH);
    float var  = sq * (1.f / HH) - mean * mean;
    float inv  = rsqrtf(var + 1e-5f);
#pragma unroll
    for (int i = 0; i < 4; i++) {
        int c = (i * 32 + lane) * 4;
        float4 gg = *reinterpret_cast<const float4*>(g + c);
        float4 bb = *reinterpret_cast<const float4*>(b + c);
        __half2 p0 = __floats2half2_rn((v[i].x - mean) * inv * gg.x + bb.x,
                                       (v[i].y - mean) * inv * gg.y + bb.y);
        __half2 p1 = __floats2half2_rn((v[i].z - mean) * inv * gg.z + bb.z,
                                       (v[i].w - mean) * inv * gg.w + bb.w);
        __half* yr = y + pk_idx(warp, c, HH);
        *reinterpret_cast<__half2*>(yr)     = p0;
        *reinterpret_cast<__half2*>(yr + 2) = p1;
    }
}

// == fp16 TC GEMM v7: 128x128 tile, KC=64, operands PACKED in global ->
//    TWO 16KB cp.async.bulk per stage, XOR-swizzle LDSM (v5 addressing), 2 CTA/SM ==
#define G_STG 16384
#define GEMM_SMEM (6*G_STG)

template <int MODE>
__global__ __launch_bounds__(256, 2) void gemm_h(
    const __half* __restrict__ Ap, const __half* __restrict__ Wp,
    void* __restrict__ Cv, int N, int K,
    const float* __restrict__ bias, const float* __restrict__ bias2,
    const float* __restrict__ res)
{
    extern __shared__ __align__(128) char sm[];
    __shared__ __align__(8) uint64_t mbars[3];
    const uint32_t abase = smem_u32(sm);
    const uint32_t bbase = abase + 3 * G_STG;
    const uint32_t mb = smem_u32(mbars);

    const int tid = threadIdx.x;
    const int wid = tid >> 5, lane = tid & 31;
    const int wm = wid & 1, wn = wid >> 1;
    const int g = lane >> 2, tq = lane & 3;
    const int m0 = blockIdx.y * 128, n0 = blockIdx.x * 128;
    const int nch = K >> 6;

    if (tid < 3) MBARRIER_INIT(mb + tid * 8, 1);
    __syncthreads();

    float acc[4][4][4];
#pragma unroll
    for (int i = 0; i < 4; i++)
#pragma unroll
        for (int j = 0; j < 4; j++)
#pragma unroll
            for (int q = 0; q < 4; q++) acc[i][j][q] = 0.f;

    const __half* Asrc = Ap + (size_t)blockIdx.y * nch * 8192;
    const __half* Bsrc = Wp + (size_t)blockIdx.x * nch * 8192;

    auto issue = [&](int buf, int ch) {
        if (tid == 0) {
            MBARRIER_EXPECT_TX(mb + buf * 8, 32768u);
            cp_bulk(abase + buf * G_STG, Asrc + (size_t)ch * 8192, 16384u, mb + buf * 8);
            cp_bulk(bbase + buf * G_STG, Bsrc + (size_t)ch * 8192, 16384u, mb + buf * 8);
        }
    };

    issue(0, 0);
    issue(1, 1);
    for (int s = 0; s < nch; s++) {
        const int buf = s % 3;
        MBARRIER_WAIT_PARITY(mb + buf * 8, (s / 3) & 1);
        __syncthreads();
        if (s + 2 < nch) issue((s + 2) % 3, s + 2);
#pragma unroll
        for (int ks = 0; ks < 4; ks++) {
            const int q = ks * 2 + (lane >> 4);
            unsigned af[4][4], bf[4][2];
#pragma unroll
            for (int ms = 0; ms < 4; ms++) {
                const int ar = wm * 64 + ms * 16 + (lane & 15);
                uint32_t ad = abase + buf * G_STG +
                              (uint32_t)(ar * 128 + ((q ^ (ar & 7)) << 4));
                LDSM4(af[ms][0], af[ms][1], af[ms][2], af[ms][3], ad);
            }
#pragma unroll
            for (int nb = 0; nb < 2; nb++) {
                const int br = wn * 32 + nb * 16 + (lane & 15);
                uint32_t bd = bbase + buf * G_STG +
                              (uint32_t)(br * 128 + ((q ^ (br & 7)) << 4));
                unsigned r0, r1, r2, r3;
                LDSM4(r0, r1, r2, r3, bd);
                bf[2 * nb][0] = r0; bf[2 * nb][1] = r2;
                bf[2 * nb + 1][0] = r1; bf[2 * nb + 1][1] = r3;
            }
#pragma unroll
            for (int ms = 0; ms < 4; ms++)
#pragma unroll
                for (int ns = 0; ns < 4; ns++)
                    mma_f16(acc[ms][ns], af[ms], bf[ns]);
        }
    }

    float* Cf = reinterpret_cast<float*>(Cv);
    __half* Ch = reinterpret_cast<__half*>(Cv);
#pragma unroll
    for (int ms = 0; ms < 4; ms++) {
#pragma unroll
        for (int ns = 0; ns < 4; ns++) {
            const int col = n0 + wn * 32 + ns * 8 + tq * 2;
            const float b0 = bias[col], b1 = bias[col + 1];
#pragma unroll
            for (int half = 0; half < 2; half++) {
                const int row = m0 + wm * 64 + ms * 16 + g + half * 8;
                float v0 = acc[ms][ns][half * 2 + 0] + b0;
                float v1 = acc[ms][ns][half * 2 + 1] + b1;
                if (MODE == 0) {
                    v0 += bias2[col]; v1 += bias2[col + 1];
                    *reinterpret_cast<__half2*>(Ch + (size_t)row * N + col) =
                        __floats2half2_rn(v0, v1);
                } else if (MODE == 1) {
                    v0 = 0.5f * v0 * (1.f + erff(v0 * 0.7071067811865475f));
                    v1 = 0.5f * v1 * (1.f + erff(v1 * 0.7071067811865475f));
                    // FC output packed for gemm<2>'s A operand (K=2048)
                    *reinterpret_cast<__half2*>(Ch + pk_idx(row, col, H4)) =
                        __floats2half2_rn(v0, v1);
                } else {
                    const float2 rr = *reinterpret_cast<const float2*>(res + (size_t)row * N + col);
                    v0 += rr.x; v1 += rr.y;
                    *reinterpret_cast<float2*>(Cf + (size_t)row * N + col) = make_float2(v0, v1);
                }
            }
        }
    }
}

// ---- persistent recurrent (R11 version, 256 threads): W resident, chunked TMA H ----
// h global layout per rt-group: 4 chunks of 16KB:
//   off = rt*32768 + cg*8192 + b*128 + ((q ^ (b&7))<<3) + (j&7)  [halves]
#define R_WOFF 0
#define R_HOFF 81920
#define R_GIOFF (81920 + 65536)
#define R_GOFF (R_GIOFF + 8192)
#define R_MBAR (R_GOFF + 64*65*4)
#define REC_SMEM (R_MBAR + 32)

__global__ __launch_bounds__(256) void lstm_rec_h(
    const __half* __restrict__ Whh, const __half* __restrict__ G,
    const float* __restrict__ X, float* __restrict__ Y,
    __half* __restrict__ h0, __half* __restrict__ h1, unsigned* bar)
{
    extern __shared__ __align__(128) char rsm[];
    const uint32_t ws0 = smem_u32(rsm) + R_WOFF;
    const uint32_t hs0 = smem_u32(rsm) + R_HOFF;
    const uint32_t gi0 = smem_u32(rsm) + R_GIOFF;
    const uint32_t mb  = smem_u32(rsm) + R_MBAR;
    __half* Gin = reinterpret_cast<__half*>(rsm + R_GIOFF);
    float (*gt)[65] = reinterpret_cast<float(*)[65]>(rsm + R_GOFF);

    const int rt = blockIdx.x >> 5;
    const int ct = blockIdx.x & 31;
    const int tid = threadIdx.x;
    const int wid = tid >> 5, lane = tid & 31;
    const int wm = wid & 1, wn = wid >> 1;      // wn = gate index
    const int g = lane >> 2, tq = lane & 3;

    // one-time W load (40-pad layout)
#pragma unroll
    for (int i = 0; i < 16; i++) {
        int u = tid + i * 256;
        int c = u >> 8, rem = u & 255;
        int r = rem >> 2, q = rem & 3;
        const __half* src = Whh + (size_t)((r >> 4) * 512 + ct * 16 + (r & 15)) * HH
                            + c * 32 + q * 8;
        cpa16(ws0 + (uint32_t)(((c * 64 + r) * 40 + q * 8) * 2), src);
    }
    CP_COMMIT();
    if (tid < 4) MBARRIER_INIT(mb + tid * 8, 1);
    CP_WAIT(0);
    __syncthreads();

    float creg[4] = {0.f, 0.f, 0.f, 0.f};

    for (int t = 0; t < T_STEPS; t++) {
        const __half* hin  = (t & 1) ? h1 : h0;
        __half*       hout = (t & 1) ? h0 : h1;
        const __half* Gt = G + (size_t)t * BB * H4;

        if (tid == 0) {
#pragma unroll
            for (int cg = 0; cg < 4; cg++) {
                MBARRIER_EXPECT_TX(mb + cg * 8, 16384u);
                cp_bulk(hs0 + cg * 16384, hin + (size_t)rt * 32768 + cg * 8192,
                        16384u, mb + cg * 8);
            }
        }
#pragma unroll
        for (int i = 0; i < 2; i++) {
            int u = tid + i * 256;
            int r = u >> 3, seg = u & 7;
            int gate = seg >> 1, hq = seg & 1;
            cpa16(gi0 + (uint32_t)((r * 64 + gate * 16 + hq * 8) * 2),
                  Gt + (size_t)(rt * 64 + r) * H4 + gate * 512 + ct * 16 + hq * 8);
        }
        CP_COMMIT();

        float xv[4];
#pragma unroll
        for (int it = 0; it < 4; it++) {
            const int e = it * 256 + tid;
            const int gb = rt * 64 + (e >> 4);
            const int j = ct * 16 + (e & 15);
            xv[it] = __ldg(X + (size_t)t * BB * HH + (size_t)gb * HH + j);
        }

        float acc[2][2][4];
#pragma unroll
        for (int i = 0; i < 2; i++)
#pragma unroll
            for (int j = 0; j < 2; j++)
#pragma unroll
                for (int q = 0; q < 4; q++) acc[i][j][q] = 0.f;

        for (int s = 0; s < 16; s++) {
            if ((s & 3) == 0) MBARRIER_WAIT_PARITY(mb + (s >> 2) * 8, t & 1);
#pragma unroll
            for (int ks = 0; ks < 2; ks++) {
                const int kc = ks * 16 + ((lane >> 4) << 3);
                const int ql = (s & 3) * 4 + (kc >> 3);
                unsigned af[2][4], bf[2][2];
#pragma unroll
                for (int ms = 0; ms < 2; ms++) {
                    const int ar = wm * 32 + ms * 16 + (lane & 15);
                    uint32_t ad = hs0 + (s >> 2) * 16384 +
                                  (uint32_t)(ar * 256 + ((ql ^ (ar & 7)) << 4));
                    LDSM4(af[ms][0], af[ms][1], af[ms][2], af[ms][3], ad);
                }
                {
                    const int br = wn * 16 + (lane & 15);
                    uint32_t bd = ws0 + (uint32_t)(((s * 64 + br) * 40 + kc) * 2);
                    unsigned r0, r1, r2, r3;
                    LDSM4(r0, r1, r2, r3, bd);
                    bf[0][0] = r0; bf[0][1] = r2;
                    bf[1][0] = r1; bf[1][1] = r3;
                }
#pragma unroll
                for (int ms = 0; ms < 2; ms++)
#pragma unroll
                    for (int ns = 0; ns < 2; ns++)
                        mma_f16(acc[ms][ns], af[ms], bf[ns]);
            }
        }

        CP_WAIT(0);
        __syncthreads();

#pragma unroll
        for (int ms = 0; ms < 2; ms++) {
#pragma unroll
            for (int ns = 0; ns < 2; ns++) {
                const int ncol = ns * 8 + tq * 2;
#pragma unroll
                for (int half = 0; half < 2; half++) {
                    const int row = wm * 32 + ms * 16 + g + half * 8;
                    const __half2 gh = *reinterpret_cast<const __half2*>(
                        Gin + row * 64 + wn * 16 + ncol);
                    const float2 gi = __half22float2(gh);
                    gt[row][wn * 16 + ncol]     = acc[ms][ns][half * 2 + 0] + gi.x;
                    gt[row][wn * 16 + ncol + 1] = acc[ms][ns][half * 2 + 1] + gi.y;
                }
            }
        }
        __syncthreads();

        float hnv[4];
#pragma unroll
        for (int it = 0; it < 4; it++) {
            const int e = it * 256 + tid;
            const int b = e >> 4;
            const int jl = e & 15;
            const float ig = gt[b][jl];
            const float fg = gt[b][16 + jl];
            const float gg = gt[b][32 + jl];
            const float og = gt[b][48 + jl];
            const float cn = fsig(fg) * creg[it] + fsig(ig) * ftanh(gg);
            const float hn = fsig(og) * ftanh(cn);
            creg[it] = cn;
            hnv[it] = hn;
            const int j = ct * 16 + jl;
            const int cg = j >> 7;
            const int q = (j & 127) >> 3;
            const size_t hoff = (size_t)rt * 32768 + cg * 8192 + b * 128 +
                                ((q ^ (b & 7)) << 3) + (jl & 7);
            const __half hh = __float2half_rn(hn);
            asm volatile("st.global.cg.b16 [%0], %1;"
                         :: "l"(hout + hoff), "h"(__half_as_ushort(hh)));
        }
        __syncthreads();
        if (tid == 0) {
            __threadfence();
            atomicAdd(bar + rt, 1u);
        }
#pragma unroll
        for (int it = 0; it < 4; it++) {
            const int e = it * 256 + tid;
            const int gb = rt * 64 + (e >> 4);
            const int j = ct * 16 + (e & 15);
            Y[(size_t)t * BB * HH + (size_t)gb * HH + j] = xv[it] + hnv[it];
        }
        if (tid == 0) {
            const unsigned target = (unsigned)(t + 1) * 32u;
            while (*reinterpret_cast<volatile unsigned*>(bar + rt) < target) __nanosleep(32);
            __threadfence();
        }
        __syncthreads();
    }
}

// ---------------- output heads ----------------
__global__ __launch_bounds__(256) void heads_kernel(
    const float* __restrict__ last,
    const float* __restrict__ btn_w, const float* __restrict__ btn_b,
    const float* __restrict__ ms_w,  const float* __restrict__ ms_b,
    const float* __restrict__ cs_w,  const float* __restrict__ cs_b,
    float* __restrict__ out)
{
    int b = blockIdx.x;
    __shared__ float row[HH];
    for (int i = threadIdx.x; i < HH; i += blockDim.x) row[i] = last[(size_t)b * HH + i];
    __syncthreads();
    int warp = threadIdx.x >> 5, lane = threadIdx.x & 31;
    for (int o = warp; o < 58; o += 8) {
        const float* w; float bias; float* dst;
        if (o < 16)      { w = btn_w + o * HH;        bias = btn_b[o];      dst = out + b * 16 + o; }
        else if (o < 37) { int oo = o - 16; w = ms_w + oo * HH; bias = ms_b[oo]; dst = out + 4096 + b * 21 + oo; }
        else             { int oo = o - 37; w = cs_w + oo * HH; bias = cs_b[oo]; dst = out + 9472 + b * 21 + oo; }
        float s = 0.f;
        for (int k = lane; k < HH; k += 32) s += row[k] * w[k];
#pragma unroll
        for (int off = 16; off; off >>= 1) s += __shfl_down_sync(0xffffffffu, s, off);
        if (lane == 0) *dst = s + bias;
    }
}

// ---------------- launch ----------------
extern "C" void kernel_launch(void* const* d_in, const int* in_sizes, int n_in,
                              void* d_out, int out_size)
{
    const float* gamestate = (const float*)d_in[0];
    const int*   stage     = (const int*)d_in[1];
    const int*   egoc      = (const int*)d_in[2];
    const int*   oppc      = (const int*)d_in[3];
    const int*   egoa      = (const int*)d_in[4];
    const int*   oppa      = (const int*)d_in[5];
    const float* emb_stage = (const float*)d_in[6];
    const float* emb_char  = (const float*)d_in[7];
    const float* emb_act   = (const float*)d_in[8];
    const float* ln1_g     = (const float*)d_in[9];
    const float* ln1_b     = (const float*)d_in[10];
    const float* w_ih      = (const float*)d_in[11];
    const float* w_hh      = (const float*)d_in[12];
    const float* b_ih      = (const float*)d_in[13];
    const float* b_hh      = (const float*)d_in[14];
    const float* ln2_g     = (const float*)d_in[15];
    const float* ln2_b     = (const float*)d_in[16];
    const float* fc_w      = (const float*)d_in[17];
    const float* fc_b      = (const float*)d_in[18];
    const float* proj_w    = (const float*)d_in[19];
    const float* proj_b    = (const float*)d_in[20];
    const float* btn_w     = (const float*)d_in[21];
    const float* btn_b     = (const float*)d_in[22];
    const float* ms_w      = (const float*)d_in[23];
    const float* ms_b      = (const float*)d_in[24];
    const float* cs_w      = (const float*)d_in[25];
    const float* cs_b      = (const float*)d_in[26];

    void *pX, *pXN, *pY, *pYN, *pG, *pFC, *ph0, *ph1, *pbar, *pWih, *pWfc, *pWpr, *pWhh;
    cudaGetSymbolAddress(&pX,  d_X);
    cudaGetSymbolAddress(&pXN, d_XN);
    cudaGetSymbolAddress(&pY,  d_Y);
    cudaGetSymbolAddress(&pYN, d_YN);
    cudaGetSymbolAddress(&pG,  d_G);
    cudaGetSymbolAddress(&pFC, d_FC);
    cudaGetSymbolAddress(&ph0, d_h0);
    cudaGetSymbolAddress(&ph1, d_h1);
    cudaGetSymbolAddress(&pbar, d_bar);
    cudaGetSymbolAddress(&pWih, d_Wih);
    cudaGetSymbolAddress(&pWfc, d_Wfc);
    cudaGetSymbolAddress(&pWpr, d_Wpr);
    cudaGetSymbolAddress(&pWhh, d_Whh);
    float*  X  = (float*)pX;   __half* XN = (__half*)pXN;
    float*  Y  = (float*)pY;   __half* YN = (__half*)pYN;
    __half* G  = (__half*)pG;  __half* FC = (__half*)pFC;
    __half* h0 = (__half*)ph0; __half* h1 = (__half*)ph1;
    __half* Wih = (__half*)pWih; __half* Wfc = (__half*)pWfc;
    __half* Wpr = (__half*)pWpr; __half* Whh = (__half*)pWhh;
    unsigned* bar = (unsigned*)pbar;

    cudaFuncSetAttribute(gemm_h<0>, cudaFuncAttributeMaxDynamicSharedMemorySize, GEMM_SMEM);
    cudaFuncSetAttribute(gemm_h<1>, cudaFuncAttributeMaxDynamicSharedMemorySize, GEMM_SMEM);
    cudaFuncSetAttribute(gemm_h<2>, cudaFuncAttributeMaxDynamicSharedMemorySize, GEMM_SMEM);
    cudaFuncSetAttribute(lstm_rec_h, cudaFuncAttributeMaxDynamicSharedMemorySize, REC_SMEM);

    const int M = T_STEPS * BB;        // 65536
    const int WN = NBLK * H4 * HH;     // 4M

    // launch order: conv+detect(1), embed_ln(2), gemm<0>(3), lstm(4 = ncu slot)
    h_conv4d<<<4 * WN / 256, 256>>>(w_ih, fc_w, proj_w, w_hh, Wih, Wfc, Wpr, Whh, WN,
                                    stage, BB * T_STEPS);
    embed_ln_kernel<<<M, 128>>>(gamestate, stage, egoc, oppc, egoa, oppa,
                                emb_stage, emb_char, emb_act, ln1_g, ln1_b);

    for (int i = 0; i < NBLK; i++) {
        if (i > 0)
            ln_kernel<<<M / 8, 256>>>(X, XN, ln1_g + i * HH, ln1_b + i * HH, M);
        gemm_h<0><<<dim3(H4 / 128, M / 128), 256, GEMM_SMEM>>>(
            XN, Wih + (size_t)i * H4 * HH, G, H4, HH,
            b_ih + i * H4, b_hh + i * H4, nullptr);

        cudaMemsetAsync(h0, 0, BB * HH * sizeof(__half), 0);
        cudaMemsetAsync(bar, 0, 4 * sizeof(unsigned), 0);
        lstm_rec_h<<<128, 256, REC_SMEM>>>(Whh + (size_t)i * H4 * HH, G, X, Y, h0, h1, bar);

        ln_kernel<<<M / 8, 256>>>(Y, YN, ln2_g + i * HH, ln2_b + i * HH, M);
        gemm_h<1><<<dim3(H4 / 128, M / 128), 256, GEMM_SMEM>>>(
            YN, Wfc + (size_t)i * H4 * HH, FC, H4, HH,
            fc_b + i * H4, nullptr, nullptr);
        gemm_h<2><<<dim3(HH / 128, M / 128), 256, GEMM_SMEM>>>(
            FC, Wpr + (size_t)i * HH * H4, X, HH, H4,
            proj_b + i * HH, nullptr, Y);
    }

    heads_kernel<<<BB, 256>>>(X + (size_t)(T_STEPS - 1) * BB * HH,
                              btn_w, btn_b, ms_w, ms_b, cs_w, cs_b,
                              (float*)d_out);
}